// round 5
// baseline (speedup 1.0000x reference)
#include <cuda_runtime.h>

// ============================================================================
// Linear slab model, closed-form parallel solution (z_init = 0 exploited).
//   z_{n+1} = a*z_n + f_n,  a = (1-dt*K1) - i*dt*fc,  f_n linear per interval.
// Within a forcing interval (ns steps, forcing f = p + q*m):
//   z_m = u + v*m + a^m * w,   v = q/(1-a), u = (p-v)/(1-a), w = z_0 - u
// Since z_init = 0, interval start states are a pure S-prefix with CONSTANT
// multiplier A = a^ns  ->  scan needs no P component at all.
// kA: per-interval S + constant-multiplier shuffle scan (thread-0 smem consts)
// kB: scan 256 block aggregates (mult B=A^1024); build g_pow / g_Apow tables
// kD: 12 outputs/thread, crossing-free fast path, coalesced float4 stores
// ============================================================================

#define SCAN_B 1024
#define MAXI   262144
#define NBMAX  (MAXI / SCAN_B)   // 256
#define POW_N  256

__device__ float4 g_uv[MAXI];     // (u.x, u.y, v.x, v.y)
__device__ float2 g_prefS[MAXI];  // block-local exclusive S prefix
__device__ float2 g_aggS[NBMAX];  // per-block aggregate
__device__ float2 g_boff[NBMAX];  // global state at start of each kA block
__device__ float2 g_pow[POW_N];   // a^m, m <= ns
__device__ float2 g_Apow[SCAN_B]; // A^k, k < 1024, A = a^ns

struct DevK {
    float c, d, e, inv_ns;
    int   ns, it0, j0, m0;
    int   NI, pad;
};
__device__ DevK g_k;

__device__ __forceinline__ float2 cmul(float2 a, float2 b) {
    return make_float2(fmaf(a.x, b.x, -a.y * b.y), fmaf(a.x, b.y, a.y * b.x));
}
__device__ __forceinline__ float2 cfma2(float2 A, float2 z, float2 h) {
    return make_float2(fmaf(A.x, z.x, fmaf(-A.y, z.y, h.x)),
                       fmaf(A.x, z.y, fmaf( A.y, z.x, h.y)));
}
__device__ __forceinline__ float2 cpow(float2 a, int e) {
    float2 r = make_float2(1.0f, 0.0f);
    while (e) { if (e & 1) r = cmul(r, a); a = cmul(a, a); e >>= 1; }
    return r;
}
__device__ __forceinline__ float2 cinv(float2 a) {
    float s = 1.0f / fmaf(a.x, a.x, a.y * a.y);
    return make_float2(a.x * s, -a.y * s);
}

// ---------------- kA ---------------------------------------------------------
__global__ __launch_bounds__(SCAN_B) void kA(
    const float* __restrict__ pk,
    const float* __restrict__ TAx, const float* __restrict__ TAy,
    const float* __restrict__ fcp,
    const int* __restrict__ t0p, const int* __restrict__ dtp,
    int nl, int nsteps)
{
    __shared__ DevK   skk;
    __shared__ float2 sInv1ma;
    __shared__ float2 sLane[32];   // A^1 .. A^32
    __shared__ float2 sWoff[5];    // A^{32*2^k}, k=0..4
    __shared__ float2 wAgg[32];
    __shared__ float2 sS[SCAN_B];

    const int tid  = threadIdx.x;
    const int lane = tid & 31;
    const int wrp  = tid >> 5;

    if (tid == 0) {
        DevK dk;
        int   dti = dtp[0];
        float dtf = (float)dti;
        dk.c = 1.0f - dtf * expf(pk[1]);
        dk.d = dtf * fcp[0];
        dk.e = dtf * expf(pk[0]);
        dk.ns = 3600 / dti;
        dk.inv_ns = 1.0f / (float)dk.ns;
        dk.it0 = t0p[0] / dti;
        dk.j0 = dk.it0 / dk.ns;
        dk.m0 = dk.it0 - dk.j0 * dk.ns;
        dk.NI = (dk.m0 + nsteps + dk.ns - 1) / dk.ns;
        dk.pad = 0;
        skk = dk;
        if (blockIdx.x == 0) g_k = dk;
        sInv1ma = cinv(make_float2(1.0f - dk.c, dk.d));

        float2 a = make_float2(dk.c, -dk.d);
        float2 A = cpow(a, dk.ns);
        float2 p = A;
        sLane[0] = A;
        for (int i = 1; i < 32; i++) { p = cmul(p, A); sLane[i] = p; }
        float2 q = p;                       // A^32
        for (int i = 0; i < 5; i++) { sWoff[i] = q; q = cmul(q, q); }
    }
    __syncthreads();

    const DevK k = skk;
    const int  s = blockIdx.x * SCAN_B + tid;
    const bool valid = (s < k.NI);
    const float2 a = make_float2(k.c, -k.d);

    float2 S = make_float2(0.0f, 0.0f);
    if (valid) {
        int j  = k.j0 + s;
        int i1 = min(j,     nl - 1);
        int i2 = min(j + 1, nl - 1);
        float Tx0 = TAx[i1], Tx1 = TAx[i2];
        float Ty0 = TAy[i1], Ty1 = TAy[i2];
        float2 inv1ma = sInv1ma;
        float2 p = make_float2(k.e * Tx0, k.e * Ty0);
        float  eq = k.e * k.inv_ns;
        float2 q = make_float2(eq * (Tx1 - Tx0), eq * (Ty1 - Ty0));
        float2 v = cmul(q, inv1ma);
        float2 u = cmul(make_float2(p.x - v.x, p.y - v.y), inv1ma);
        g_uv[s] = make_float4(u.x, u.y, v.x, v.y);

        int    msta = (s == 0) ? k.m0 : 0;
        float2 P    = (msta == 0) ? sLane[0] : cpow(a, k.ns - msta);
        float fns = (float)k.ns, fm = (float)msta;
        float2 zend = make_float2(fmaf(v.x, fns, u.x), fmaf(v.y, fns, u.y));
        float2 zsta = make_float2(fmaf(v.x, fm,  u.x), fmaf(v.y, fm,  u.y));
        float2 Ps   = cmul(P, zsta);
        S = make_float2(zend.x - Ps.x, zend.y - Ps.y);
    }

    const unsigned full = 0xffffffffu;
    // warp-local inclusive scan with constant multipliers A^off
#pragma unroll
    for (int rk = 0; rk < 5; rk++) {
        int off = 1 << rk;
        float2 M = sLane[off - 1];
        float pSx = __shfl_up_sync(full, S.x, off);
        float pSy = __shfl_up_sync(full, S.y, off);
        if (lane >= off) S = cfma2(M, make_float2(pSx, pSy), S);
    }
    if (lane == 31) wAgg[wrp] = S;
    __syncthreads();
    if (wrp == 0) {
        float2 T = wAgg[lane];
#pragma unroll
        for (int rk = 0; rk < 5; rk++) {
            int off = 1 << rk;
            float2 M = sWoff[rk];              // A^{32*off}
            float pTx = __shfl_up_sync(full, T.x, off);
            float pTy = __shfl_up_sync(full, T.y, off);
            if (lane >= off) T = cfma2(M, make_float2(pTx, pTy), T);
        }
        wAgg[lane] = T;
    }
    __syncthreads();
    if (wrp > 0) {
        S = cfma2(sLane[lane], wAgg[wrp - 1], S);   // A^{lane+1} * prevwarps + S
    }
    sS[tid] = S;
    __syncthreads();
    if (valid)
        g_prefS[s] = (tid > 0) ? sS[tid - 1] : make_float2(0.0f, 0.0f);
    if (tid == SCAN_B - 1)
        g_aggS[blockIdx.x] = S;
}

// ---------------- kB: aggregate scan + tables --------------------------------
__global__ __launch_bounds__(NBMAX) void kB(int nsteps)
{
    __shared__ float2 sBL[32];   // B^1 .. B^32
    __shared__ float2 sBW[3];    // B^{32,64,128}
    __shared__ float2 sS[NBMAX];
    __shared__ float2 wAgg[8];

    const int tid  = threadIdx.x;
    const int lane = tid & 31;
    const int wrp  = tid >> 5;

    const DevK k = g_k;
    const float2 a = make_float2(k.c, -k.d);
    const float2 A = cpow(a, k.ns);

    // tables
    for (int i = tid; i < POW_N; i += NBMAX)
        if (i <= k.ns) g_pow[i] = cpow(a, i);
    for (int i = tid; i < SCAN_B; i += NBMAX)
        g_Apow[i] = cpow(A, i);

    if (tid == 0) {
        float2 B = cpow(A, SCAN_B);
        float2 p = B;
        sBL[0] = B;
        for (int i = 1; i < 32; i++) { p = cmul(p, B); sBL[i] = p; }
        float2 q = p;                          // B^32
        for (int i = 0; i < 3; i++) { sBW[i] = q; q = cmul(q, q); }
    }
    __syncthreads();

    const int NB = (k.NI + SCAN_B - 1) / SCAN_B;
    float2 S = (tid < NB) ? g_aggS[tid] : make_float2(0.0f, 0.0f);

    const unsigned full = 0xffffffffu;
#pragma unroll
    for (int rk = 0; rk < 5; rk++) {
        int off = 1 << rk;
        float2 M = sBL[off - 1];
        float pSx = __shfl_up_sync(full, S.x, off);
        float pSy = __shfl_up_sync(full, S.y, off);
        if (lane >= off) S = cfma2(M, make_float2(pSx, pSy), S);
    }
    if (lane == 31) wAgg[wrp] = S;
    __syncthreads();
    if (wrp == 0 && lane < 8) {
        float2 T = wAgg[lane];
#pragma unroll
        for (int rk = 0; rk < 3; rk++) {
            int off = 1 << rk;
            float2 M = sBW[rk];                // B^{32*off}
            float pTx = __shfl_up_sync(0xffu, T.x, off);
            float pTy = __shfl_up_sync(0xffu, T.y, off);
            if (lane >= off) T = cfma2(M, make_float2(pTx, pTy), T);
        }
        wAgg[lane] = T;
    }
    __syncthreads();
    if (wrp > 0)
        S = cfma2(sBL[lane], wAgg[wrp - 1], S);
    sS[tid] = S;
    __syncthreads();
    g_boff[tid] = (tid > 0) ? sS[tid - 1] : make_float2(0.0f, 0.0f);
}

// ---------------- kD: 12 outputs/thread --------------------------------------
__global__ __launch_bounds__(256) void kD(int nsteps, float* __restrict__ out)
{
    const DevK k = g_k;
    const float2 a = make_float2(k.c, -k.d);
    const int ns = k.ns, it0 = k.it0, j0 = k.j0, m0 = k.m0;

    const int t  = blockIdx.x * blockDim.x + threadIdx.x;
    const int n0 = t * 12;
    if (n0 >= nsteps) return;

    const int it = it0 + n0;
    const int sg = it / ns;
    const int r  = it - sg * ns;
    int sidx = sg - j0;

    float4 uv = __ldg(g_uv + sidx);
    float2 Sx = __ldg(g_prefS + sidx);
    float2 bo = __ldg(g_boff + (sidx >> 10));
    float2 Ap = __ldg(g_Apow + (sidx & (SCAN_B - 1)));
    float2 z0 = cfma2(Ap, bo, Sx);             // state at interval start

    float2 w;
    if (sidx == 0 && m0 != 0) {
        w = make_float2(z0.x - fmaf(uv.z, (float)m0, uv.x),
                        z0.y - fmaf(uv.w, (float)m0, uv.y));
        float2 pm = (ns < POW_N) ? __ldg(g_pow + m0) : cpow(a, m0);
        w = cmul(w, cinv(pm));
    } else {
        w = make_float2(z0.x - uv.x, z0.y - uv.y);
    }

    int   m  = r + 1;
    float fm = (float)m;
    float2 pw   = (ns < POW_N) ? __ldg(g_pow + m) : cpow(a, m);
    float2 aw   = cmul(pw, w);
    float2 base = make_float2(fmaf(uv.z, fm, uv.x), fmaf(uv.w, fm, uv.y));

    const bool fast = (r + 12 <= ns) && (n0 + 12 <= nsteps) && ((nsteps & 3) == 0);
    if (fast) {
#pragma unroll
        for (int gq = 0; gq < 3; gq++) {
            float4 Uq, Vq;
            Uq.x = base.x + aw.x; Vq.x = base.y + aw.y;
            base.x += uv.z; base.y += uv.w; aw = cmul(aw, a);
            Uq.y = base.x + aw.x; Vq.y = base.y + aw.y;
            base.x += uv.z; base.y += uv.w; aw = cmul(aw, a);
            Uq.z = base.x + aw.x; Vq.z = base.y + aw.y;
            base.x += uv.z; base.y += uv.w; aw = cmul(aw, a);
            Uq.w = base.x + aw.x; Vq.w = base.y + aw.y;
            base.x += uv.z; base.y += uv.w; aw = cmul(aw, a);
            int o = n0 + gq * 4;
            *reinterpret_cast<float4*>(out + o)          = Uq;
            *reinterpret_cast<float4*>(out + nsteps + o) = Vq;
        }
    } else {
        int lim = min(12, nsteps - n0);
        for (int kk = 0; kk < lim; kk++) {
            float2 z = make_float2(base.x + aw.x, base.y + aw.y);
            out[n0 + kk]          = z.x;
            out[nsteps + n0 + kk] = z.y;
            if (m == ns) {                     // crossing: z is next start
                sidx = min(sidx + 1, MAXI - 1);
                uv = __ldg(g_uv + sidx);
                w  = make_float2(z.x - uv.x, z.y - uv.y);
                m  = 1;
                base = make_float2(uv.x + uv.z, uv.y + uv.w);
                aw   = cmul(a, w);
            } else {
                m++;
                base.x += uv.z; base.y += uv.w;
                aw = cmul(aw, a);
            }
        }
    }
}

// ---------------- host ------------------------------------------------------
extern "C" void kernel_launch(void* const* d_in, const int* in_sizes, int n_in,
                              void* d_out, int out_size)
{
    const float* pk  = (const float*)d_in[0];
    const float* TAx = (const float*)d_in[1];
    const float* TAy = (const float*)d_in[2];
    const float* fcp = (const float*)d_in[3];
    const int*   t0p = (const int*)d_in[4];
    // d_in[5] = t1 (unused; nsteps derived from out_size)
    const int*   dtp = (const int*)d_in[6];

    const int nl     = in_sizes[1];
    const int nsteps = out_size / 2;
    float* out = (float*)d_out;

    kA<<<NBMAX, SCAN_B>>>(pk, TAx, TAy, fcp, t0p, dtp, nl, nsteps);
    kB<<<1, NBMAX>>>(nsteps);

    const int TB = 256;
    const int nthr = (nsteps + 11) / 12;
    const int GB = (nthr + TB - 1) / TB;
    kD<<<GB, TB>>>(nsteps, out);
}